// round 6
// baseline (speedup 1.0000x reference)
#include <cuda_runtime.h>
#include <cuda_bf16.h>
#include <cstdint>

// SimpleRetention — recurrent reformulation + split-bf16 tensor-core projections.
// B=32, S=1024, E=512, H=64, N_AGENTS=4, T=256, KAPPA=0.9

#define BB 32
#define SS 1024
#define EE 512
#define HH 64
#define TT 256
#define KAPPA 0.9f

// ---------------- device scratch ----------------
__device__ float g_q[BB * SS * HH];
__device__ float g_k[BB * SS * HH];
__device__ float g_v[BB * SS * HH];
__device__ int g_fmt;                          // 0=int32, 1=float32, 2=uint8
__device__ __nv_bfloat16 g_Wh[3 * HH * EE];    // split weights, [z][n][k]
__device__ __nv_bfloat16 g_Wl[3 * HH * EE];

// truncation split: hi = top-16-bits(x) as bf16, lo = bf16_trunc(x - hi)
__device__ __forceinline__ unsigned hi_mask(float x) {
    return __float_as_uint(x) & 0xFFFF0000u;
}

// ---------------- K0: prep (detect dones fmt + transpose/split W) ----------------
__global__ __launch_bounds__(256)
void prep_kernel(const void* __restrict__ dones,
                 const float* __restrict__ Wq,
                 const float* __restrict__ Wk,
                 const float* __restrict__ Wv) {
    const int tid = threadIdx.x;
    if (blockIdx.x == 0) {
        // ---- detect dtype of dones over first 8192 words (32 KB, min size) ----
        __shared__ int s_f32, s_u8;
        if (tid == 0) { s_f32 = 0; s_u8 = 0; }
        __syncthreads();
        const uint4* w4 = (const uint4*)dones;
        int lf = 0, lu = 0;
#pragma unroll
        for (int r = 0; r < 8; r++) {           // 256 thr * 8 = 2048 uint4 = 8192 words
            uint4 v = w4[tid + r * 256];
            unsigned a[4] = {v.x, v.y, v.z, v.w};
#pragma unroll
            for (int e = 0; e < 4; e++) {
                if (a[e] == 0x3F800000u) lf = 1;
                else if (a[e] > 1u) lu = 1;     // multi-byte packing => uint8
            }
        }
        if (lf) s_f32 = 1;
        if (lu) s_u8 = 1;
        __syncthreads();
        if (tid == 0) g_fmt = s_f32 ? 1 : (s_u8 ? 2 : 0);
    } else {
        // ---- transpose + split one W matrix: [512][64] f32 -> [64][512] bf16 x2 ----
        const int z = blockIdx.x - 1;
        const float* W = (z == 0) ? Wq : (z == 1) ? Wk : Wv;
        __nv_bfloat16* Wh = &g_Wh[z * HH * EE];
        __nv_bfloat16* Wl = &g_Wl[z * HH * EE];
        __shared__ float tile[64][65];
        for (int kt = 0; kt < 8; kt++) {
#pragma unroll
            for (int r = 0; r < 16; r++) {
                int idx = tid + r * 256;
                int row = idx >> 6, col = idx & 63;
                tile[row][col] = W[(size_t)(kt * 64 + row) * HH + col];
            }
            __syncthreads();
#pragma unroll
            for (int r = 0; r < 16; r++) {
                int idx = tid + r * 256;
                int n = idx >> 6, kl = idx & 63;
                float x = tile[kl][n];
                unsigned hb = hi_mask(x);
                float lo = x - __uint_as_float(hb);
                unsigned lb = __float_as_uint(lo);
                size_t o = (size_t)n * EE + kt * 64 + kl;
                Wh[o] = __ushort_as_bfloat16((unsigned short)(hb >> 16));
                Wl[o] = __ushort_as_bfloat16((unsigned short)(lb >> 16));
            }
            __syncthreads();
        }
    }
}

// ---------------- K1: split-bf16 tensor-core projection ----------------
// Y[32768,64] = X[32768,512] @ W[512,64].  BM=128, KC=32, 256 threads (8 warps),
// 2 blocks/SM so cross-block overlap hides barrier + staging latency.
#define BM 128
#define KC 32
#define XSTR 40   // 80 B = 20 banks -> conflict-free frags
#define WSTR 40

__device__ __forceinline__ void mma16816(float& c0, float& c1, float& c2, float& c3,
                                         uint32_t a0, uint32_t a1, uint32_t a2, uint32_t a3,
                                         uint32_t b0, uint32_t b1) {
    asm volatile(
        "mma.sync.aligned.m16n8k16.row.col.f32.bf16.bf16.f32 "
        "{%0,%1,%2,%3}, {%4,%5,%6,%7}, {%8,%9}, {%0,%1,%2,%3};\n"
        : "+f"(c0), "+f"(c1), "+f"(c2), "+f"(c3)
        : "r"(a0), "r"(a1), "r"(a2), "r"(a3), "r"(b0), "r"(b1));
}

__global__ __launch_bounds__(256, 2)
void proj_kernel(const float* __restrict__ in_key,
                 const float* __restrict__ in_query,
                 const float* __restrict__ in_value) {
    const float* X;
    float* Y;
    switch (blockIdx.z) {
        case 0:  X = in_query; Y = g_q; break;
        case 1:  X = in_key;   Y = g_k; break;
        default: X = in_value; Y = g_v; break;
    }
    const __nv_bfloat16* Wh = &g_Wh[blockIdx.z * HH * EE];
    const __nv_bfloat16* Wl = &g_Wl[blockIdx.z * HH * EE];

    __shared__ __nv_bfloat16 Xh[BM * XSTR];   // 10240 B
    __shared__ __nv_bfloat16 Xl[BM * XSTR];
    __shared__ __nv_bfloat16 Whs[HH * WSTR];  // 5120 B
    __shared__ __nv_bfloat16 Wls[HH * WSTR];

    const int tid  = threadIdx.x;
    const int wid  = tid >> 5;
    const int lane = tid & 31;
    const int g    = lane >> 2;
    const int t    = lane & 3;
    const int m0   = blockIdx.x * BM;
    const int m0w  = wid * 16;

    const int xrow = tid >> 3;            // 0..31 (x4 over r)
    const int xc4  = (tid & 7) * 4;
    const int wrow = tid >> 2;            // 0..63
    const int wseg = (tid & 3) * 8;

    float c[8][4];
#pragma unroll
    for (int nt = 0; nt < 8; nt++)
#pragma unroll
        for (int e = 0; e < 4; e++) c[nt][e] = 0.f;

    // ---- prologue: prefetch chunk 0 ----
    float4 xr[4];
    uint4 whr, wlr;
#pragma unroll
    for (int r = 0; r < 4; r++)
        xr[r] = *(const float4*)&X[(size_t)(m0 + xrow + r * 32) * EE + xc4];
    whr = *(const uint4*)&Wh[(size_t)wrow * EE + wseg];
    wlr = *(const uint4*)&Wl[(size_t)wrow * EE + wseg];

    for (int kt = 0; kt < EE; kt += KC) {
        // ---- stage prefetched regs into smem (with X split) ----
#pragma unroll
        for (int r = 0; r < 4; r++) {
            int row = xrow + r * 32;
            float xs[4] = {xr[r].x, xr[r].y, xr[r].z, xr[r].w};
            unsigned hb[4], lb[4];
#pragma unroll
            for (int e = 0; e < 4; e++) {
                hb[e] = hi_mask(xs[e]);
                lb[e] = __float_as_uint(xs[e] - __uint_as_float(hb[e]));
            }
            int base = row * XSTR + xc4;
            uint2 ph = make_uint2(__byte_perm(hb[0], hb[1], 0x7632),
                                  __byte_perm(hb[2], hb[3], 0x7632));
            uint2 pl = make_uint2(__byte_perm(lb[0], lb[1], 0x7632),
                                  __byte_perm(lb[2], lb[3], 0x7632));
            *(uint2*)&Xh[base] = ph;
            *(uint2*)&Xl[base] = pl;
        }
        *(uint4*)&Whs[wrow * WSTR + wseg] = whr;
        *(uint4*)&Wls[wrow * WSTR + wseg] = wlr;
        __syncthreads();

        // ---- prefetch next chunk (overlaps with MMAs below) ----
        if (kt + KC < EE) {
#pragma unroll
            for (int r = 0; r < 4; r++)
                xr[r] = *(const float4*)&X[(size_t)(m0 + xrow + r * 32) * EE + kt + KC + xc4];
            whr = *(const uint4*)&Wh[(size_t)wrow * EE + kt + KC + wseg];
            wlr = *(const uint4*)&Wl[(size_t)wrow * EE + kt + KC + wseg];
        }

        // ---- compute: 2 k-steps of 16 ----
#pragma unroll
        for (int ks = 0; ks < 2; ks++) {
            const int kb = ks * 16;
            const int ra = (m0w + g) * XSTR + kb + t * 2;
            uint32_t ah0 = *(const uint32_t*)&Xh[ra];
            uint32_t ah1 = *(const uint32_t*)&Xh[ra + 8 * XSTR];
            uint32_t ah2 = *(const uint32_t*)&Xh[ra + 8];
            uint32_t ah3 = *(const uint32_t*)&Xh[ra + 8 * XSTR + 8];
            uint32_t al0 = *(const uint32_t*)&Xl[ra];
            uint32_t al1 = *(const uint32_t*)&Xl[ra + 8 * XSTR];
            uint32_t al2 = *(const uint32_t*)&Xl[ra + 8];
            uint32_t al3 = *(const uint32_t*)&Xl[ra + 8 * XSTR + 8];
#pragma unroll
            for (int nt = 0; nt < 8; nt++) {
                const int rb = (nt * 8 + g) * WSTR + kb + t * 2;
                uint32_t bh0 = *(const uint32_t*)&Whs[rb];
                uint32_t bh1 = *(const uint32_t*)&Whs[rb + 8];
                uint32_t bl0 = *(const uint32_t*)&Wls[rb];
                uint32_t bl1 = *(const uint32_t*)&Wls[rb + 8];
                mma16816(c[nt][0], c[nt][1], c[nt][2], c[nt][3],
                         ah0, ah1, ah2, ah3, bh0, bh1);
                mma16816(c[nt][0], c[nt][1], c[nt][2], c[nt][3],
                         ah0, ah1, ah2, ah3, bl0, bl1);
                mma16816(c[nt][0], c[nt][1], c[nt][2], c[nt][3],
                         al0, al1, al2, al3, bh0, bh1);
            }
        }
        __syncthreads();
    }

    // ---- epilogue ----
#pragma unroll
    for (int nt = 0; nt < 8; nt++) {
        const int col = nt * 8 + t * 2;
        const size_t r0 = (size_t)(m0 + m0w + g) * HH + col;
        const size_t r1 = (size_t)(m0 + m0w + g + 8) * HH + col;
        *(float2*)&Y[r0] = make_float2(c[nt][0], c[nt][1]);
        *(float2*)&Y[r1] = make_float2(c[nt][2], c[nt][3]);
    }
}

// ---------------- K2: recurrent scan ----------------
// 512 threads: warp w (0..15) owns j = jbase + w; lane owns i-strip of 2.
// Register-prefetch of next chunk hides gmem latency behind compute.
#define CH 8
__global__ __launch_bounds__(512)
void scan_kernel(const float* __restrict__ hstate,
                 const void* __restrict__ dones,
                 float* __restrict__ out,
                 int write_h) {
    const int b = blockIdx.x >> 2;
    const int jblk = blockIdx.x & 3;
    const int jbase = jblk * 16;

    const int tid  = threadIdx.x;
    const int warp = tid >> 5;        // 0..15
    const int lane = tid & 31;
    const int j    = jbase + warp;
    const int i0   = lane * 2;

    __shared__ float q_sm[CH * 4 * HH];   // 2048 floats
    __shared__ float k_sm[CH * 4 * HH];
    __shared__ float v_sm[CH * 4 * 16];   // only this block's 16 j-columns
    __shared__ float sc[TT];

    // decode this batch's dones (fmt detected by prep kernel)
    if (tid < TT) {
        const int fmt = g_fmt;
        const int pos = b * SS + 4 * tid;
        bool d;
        if (fmt == 2) d = ((const unsigned char*)dones)[pos] != 0;
        else          d = ((const unsigned*)dones)[pos] != 0u;
        sc[tid] = d ? 0.f : KAPPA;
    }

    float S0 = hstate[(size_t)b * HH * HH + i0 * HH + j];
    float S1 = hstate[(size_t)b * HH * HH + (i0 + 1) * HH + j];

    const size_t base = (size_t)b * SS * HH;

    // staging coordinates
    const int vsl = tid >> 4;          // 0..31 slot
    const int vc  = tid & 15;          // 0..15 column

    // ---- prologue: prefetch chunk 0 into regs ----
    float4 qr, kr;
    float vr;
    {
        const size_t coff = base;
        qr = *(const float4*)&g_q[coff + tid * 4];
        kr = *(const float4*)&g_k[coff + tid * 4];
        vr = g_v[coff + vsl * HH + jbase + vc];
    }

    for (int tc = 0; tc < TT / CH; tc++) {
        __syncthreads();   // previous chunk's smem fully consumed
        *(float4*)&q_sm[tid * 4] = qr;
        *(float4*)&k_sm[tid * 4] = kr;
        v_sm[vsl * 16 + vc] = vr;
        __syncthreads();

        // prefetch next chunk (LDG latency hidden behind compute below)
        if (tc + 1 < TT / CH) {
            const size_t coff = base + (size_t)(tc + 1) * (CH * 4 * HH);
            qr = *(const float4*)&g_q[coff + tid * 4];
            kr = *(const float4*)&g_k[coff + tid * 4];
            vr = g_v[coff + vsl * HH + jbase + vc];
        }

#pragma unroll
        for (int tl = 0; tl < CH; tl++) {
            const float scale = sc[tc * CH + tl];
            S0 *= scale; S1 *= scale;

#pragma unroll
            for (int a = 0; a < 4; a++) {
                const int sl = tl * 4 + a;
                float2 kv = *(const float2*)&k_sm[sl * HH + i0];
                float2 qv = *(const float2*)&q_sm[sl * HH + i0];
                float vj = v_sm[sl * 16 + warp];
                S0 += kv.x * vj;
                S1 += kv.y * vj;
                float acc = qv.x * S0 + qv.y * S1;
                acc += __shfl_xor_sync(0xffffffffu, acc, 1);
                acc += __shfl_xor_sync(0xffffffffu, acc, 2);
                acc += __shfl_xor_sync(0xffffffffu, acc, 4);
                acc += __shfl_xor_sync(0xffffffffu, acc, 8);
                acc += __shfl_xor_sync(0xffffffffu, acc, 16);
                if (lane == a)
                    out[base + (size_t)(tc * CH * 4 + sl) * HH + j] = acc;
            }
        }
    }

    if (write_h) {
        float* h_out = out + (size_t)BB * SS * HH + (size_t)b * HH * HH;
        h_out[i0 * HH + j] = S0;
        h_out[(i0 + 1) * HH + j] = S1;
    }
}

// ---------------- host launcher ----------------
extern "C" void kernel_launch(void* const* d_in, const int* in_sizes, int n_in,
                              void* d_out, int out_size) {
    const float* key    = (const float*)d_in[0];
    const float* query  = (const float*)d_in[1];
    const float* value  = (const float*)d_in[2];
    const float* hstate = (const float*)d_in[3];
    const void*  dones  = d_in[4];
    const float* Wq     = (const float*)d_in[5];
    const float* Wk     = (const float*)d_in[6];
    const float* Wv     = (const float*)d_in[7];
    float* out = (float*)d_out;

    int write_h = (out_size >= BB * SS * HH + BB * HH * HH) ? 1 : 0;

    prep_kernel<<<4, 256>>>(dones, Wq, Wk, Wv);
    dim3 pg(SS * BB / BM, 1, 3);   // 256 x 1 x 3
    proj_kernel<<<pg, 256>>>(key, query, value);
    scan_kernel<<<BB * 4, 512>>>(hstate, dones, out, write_h);
}